// round 1
// baseline (speedup 1.0000x reference)
#include <cuda_runtime.h>

// Top-8 over 128 experts per token + softmax over the selected logits.
// Output layout: d_out[0 .. T*8)        = expert_weights (float32, row-major [T,8])
//                d_out[T*8 .. 2*T*8)   = indices cast to float32 (row-major [T,8])
//
// One warp per token. Each lane holds 4 contiguous expert logits (float4 load,
// fully coalesced). Logits are mapped to order-preserving uint32 keys so all
// comparisons/reductions are integer. 8 exact selection rounds:
//   m  = REDUX.UMAX over per-lane max of remaining values
//   cm = REDUX.UMIN over expert index among lanes holding value == m
//        (exact jax.lax.top_k tie-break: value desc, then index asc)
//   remove winner (predicated), lane r captures (m, cm).
// Epilogue: softmax over the 8 captured values via octet shuffle reduction.

#define NUM_EXPERTS 128
#define TOPK 8
#define WARPS_PER_BLOCK 8

static __device__ __forceinline__ unsigned ford(float f) {
    int s = __float_as_int(f);
    return (unsigned)(s ^ ((s >> 31) | 0x80000000));
}
static __device__ __forceinline__ float iford(unsigned u) {
    int t = (int)u;
    int xorval = (~(t >> 31)) | 0x80000000;
    return __int_as_float(t ^ xorval);
}

__global__ __launch_bounds__(WARPS_PER_BLOCK * 32, 8)
void topk_softmax_kernel(const float* __restrict__ gate,
                         float* __restrict__ out_w,
                         float* __restrict__ out_i,
                         int tokens) {
    const int lane = threadIdx.x & 31;
    const int token = blockIdx.x * WARPS_PER_BLOCK + (threadIdx.x >> 5);
    if (token >= tokens) return;

    // Coalesced vector load: lane owns experts [4*lane, 4*lane+3]
    const float4 v4 =
        reinterpret_cast<const float4*>(gate + (size_t)token * NUM_EXPERTS)[lane];

    unsigned v0 = ford(v4.x);
    unsigned v1 = ford(v4.y);
    unsigned v2 = ford(v4.z);
    unsigned v3 = ford(v4.w);
    const unsigned base = (unsigned)(lane * 4);

    unsigned my_v = 0u;   // captured key for lane < 8
    unsigned my_i = 0u;   // captured expert index for lane < 8
    unsigned m0 = 0u;     // round-0 max (warp-uniform), softmax stabilizer

#pragma unroll
    for (int r = 0; r < TOPK; ++r) {
        unsigned lm = max(max(v0, v1), max(v2, v3));
        unsigned m = __reduce_max_sync(0xffffffffu, lm);

        // smallest expert index among slots holding the max value
        unsigned c = 0xffffffffu;
        c = (v3 == m) ? (base + 3u) : c;
        c = (v2 == m) ? (base + 2u) : c;
        c = (v1 == m) ? (base + 1u) : c;
        c = (v0 == m) ? (base + 0u) : c;
        unsigned cm = __reduce_min_sync(0xffffffffu, c);

        // remove the winner (only the owning lane matches)
        v0 = (base + 0u == cm) ? 0u : v0;
        v1 = (base + 1u == cm) ? 0u : v1;
        v2 = (base + 2u == cm) ? 0u : v2;
        v3 = (base + 3u == cm) ? 0u : v3;

        if (lane == r) { my_v = m; my_i = cm; }
        if (r == 0) m0 = m;
    }

    // Softmax over the 8 selected logits (held by lanes 0..7, in rank order).
    const float fmax = iford(m0);
    // lanes >= 8 compute garbage but never write; my_v=0 there -> finite.
    const float fv = iford(my_v);
    float e = __expf(fv - fmax);
    float s = e;
    s += __shfl_xor_sync(0xffffffffu, s, 4);
    s += __shfl_xor_sync(0xffffffffu, s, 2);
    s += __shfl_xor_sync(0xffffffffu, s, 1);
    const float w = e * __frcp_rn(s);

    if (lane < TOPK) {
        const size_t o = (size_t)token * TOPK + lane;
        out_w[o] = w;
        out_i[o] = (float)my_i;   // indices as numeric float32
    }
}

extern "C" void kernel_launch(void* const* d_in, const int* in_sizes, int n_in,
                              void* d_out, int out_size) {
    (void)n_in; (void)out_size;
    const float* gate = (const float*)d_in[0];
    const int tokens = in_sizes[0] / NUM_EXPERTS;

    float* out_w = (float*)d_out;
    float* out_i = out_w + (size_t)tokens * TOPK;

    const int threads = WARPS_PER_BLOCK * 32;
    const int blocks = (tokens + WARPS_PER_BLOCK - 1) / WARPS_PER_BLOCK;
    topk_softmax_kernel<<<blocks, threads>>>(gate, out_w, out_i, tokens);
}

// round 3
// speedup vs baseline: 1.4426x; 1.4426x over previous
#include <cuda_runtime.h>

// Top-8 of 128 experts per token + softmax over selected logits.
// d_out layout: [0, T*8)  = weights (f32);  [T*8, 2*T*8) = indices as f32.
//
// One warp per token, lane owns 4 contiguous experts (float4 load).
// Keys: order-preserving float->uint transform (exact).
// Prologue: each lane sorts its 4 keys descending (stable by slot; the single
// CAS where a later slot can meet an earlier slot with equal value uses a
// composite (value, slot) predicate). Expert indices are packed as bytes into
// one register, current head in the MSB.
// Per round r:
//   m  = REDUX.UMAX(head)                       -- warp max value
//   c  = REDUX.UMIN(head==m ? pack : ~0)        -- exact min-index tie-break;
//        winner's expert index = c >> 24 (MSB compare, heads have distinct idx)
//   winner lane (cand==c) shifts its list; sentinel 0 shifted into the tail so
//   an exhausted lane can never win again.
// Epilogue: lane<8 picks (m[lane], c[lane]) via a select tree (REDUX outputs
// are warp-uniform), softmax over the octet via 3 shfl.xor.

#define NUM_EXPERTS 128
#define TOPK 8
#define WARPS_PER_BLOCK 8

static __device__ __forceinline__ unsigned ford(float f) {
    int s = __float_as_int(f);
    return (unsigned)(s ^ ((s >> 31) | 0x80000000));
}
static __device__ __forceinline__ float iford(unsigned u) {
    int t = (int)u;
    return __int_as_float(t ^ ((~(t >> 31)) | 0x80000000));
}

__global__ __launch_bounds__(WARPS_PER_BLOCK * 32, 8)
void topk_softmax_kernel(const float* __restrict__ gate,
                         float* __restrict__ out_w,
                         float* __restrict__ out_i,
                         int tokens) {
    const int lane = threadIdx.x & 31;
    const int token = blockIdx.x * WARPS_PER_BLOCK + (threadIdx.x >> 5);
    if (token >= tokens) return;

    const float4 v4 =
        reinterpret_cast<const float4*>(gate + (size_t)token * NUM_EXPERTS)[lane];

    unsigned k0 = ford(v4.x);
    unsigned k1 = ford(v4.y);
    unsigned k2 = ford(v4.z);
    unsigned k3 = ford(v4.w);

    // ---- sort lane's 4 keys descending, stable by slot ----
    unsigned s0, s1, s2, s3;
    {
        // CAS(0,1): initial slots are 0,1 -> strict < is tie-correct
        bool p = k0 < k1;
        unsigned hi = max(k0, k1), lo = min(k0, k1);
        k0 = hi; k1 = lo; s0 = p ? 1u : 0u; s1 = p ? 0u : 1u;
    }
    {
        // CAS(2,3)
        bool p = k2 < k3;
        unsigned hi = max(k2, k3), lo = min(k2, k3);
        k2 = hi; k3 = lo; s2 = p ? 3u : 2u; s3 = p ? 2u : 3u;
    }
    {
        // CAS(0,2): pos0 slot in {0,1}, pos2 slot in {2,3} -> ties keep pos0
        bool p = k0 < k2;
        unsigned hi = max(k0, k2), lo = min(k0, k2);
        k0 = hi; k2 = lo;
        unsigned ns0 = p ? s2 : s0, ns2 = p ? s0 : s2; s0 = ns0; s2 = ns2;
    }
    {
        // CAS(1,3): same slot-range argument -> strict < OK
        bool p = k1 < k3;
        unsigned hi = max(k1, k3), lo = min(k1, k3);
        k1 = hi; k3 = lo;
        unsigned ns1 = p ? s3 : s1, ns3 = p ? s1 : s3; s1 = ns1; s3 = ns3;
    }
    {
        // CAS(1,2): only CAS where pos2 may hold a LOWER slot than pos1 with
        // equal value -> composite predicate (value, then slot asc).
        bool p = (k1 < k2) || (k1 == k2 && s1 > s2);
        unsigned hi = max(k1, k2), lo = min(k1, k2);
        k1 = hi; k2 = lo;
        unsigned ns1 = p ? s2 : s1, ns2 = p ? s1 : s2; s1 = ns1; s2 = ns2;
    }

    // pack expert indices (base+slot) as bytes, head in MSB
    unsigned pack = (((((s0 << 8) | s1) << 8) | s2) << 8) | s3;
    pack += (unsigned)lane * 0x04040404u;   // base = 4*lane added to every byte

    // ---- 8 selection rounds ----
    unsigned m[TOPK], c[TOPK];
#pragma unroll
    for (int r = 0; r < TOPK; ++r) {
        unsigned mr = __reduce_max_sync(0xffffffffu, k0);
        unsigned cand = (k0 == mr) ? pack : 0xffffffffu;
        unsigned cr = __reduce_min_sync(0xffffffffu, cand);
        m[r] = mr; c[r] = cr;
        if (r < TOPK - 1) {
            bool win = (cand == cr);
            k0 = win ? k1 : k0;
            k1 = win ? k2 : k1;
            k2 = win ? k3 : k2;
            k3 = win ? 0u : k3;            // sentinel: exhausted lane never re-wins
            pack = win ? (pack << 8) : pack;
        }
    }

    // ---- epilogue: lane<8 takes rank=lane via select tree (values uniform) ----
    const bool b0 = (lane & 1) != 0;
    const bool b1 = (lane & 2) != 0;
    const bool b2 = (lane & 4) != 0;

    unsigned ma = b0 ? m[1] : m[0];
    unsigned mb = b0 ? m[3] : m[2];
    unsigned mc = b0 ? m[5] : m[4];
    unsigned md = b0 ? m[7] : m[6];
    unsigned me_ = b1 ? mb : ma;
    unsigned mf = b1 ? md : mc;
    unsigned mv = b2 ? mf : me_;

    unsigned ca = b0 ? c[1] : c[0];
    unsigned cb = b0 ? c[3] : c[2];
    unsigned cc = b0 ? c[5] : c[4];
    unsigned cd = b0 ? c[7] : c[6];
    unsigned ce = b1 ? cb : ca;
    unsigned cf = b1 ? cd : cc;
    unsigned cv = b2 ? cf : ce;

    const float vmax = iford(m[0]);
    const float val = iford(mv);
    float e = __expf(val - vmax);        // <= 1 for lanes 0..7
    float s = e;
    s += __shfl_xor_sync(0xffffffffu, s, 1);
    s += __shfl_xor_sync(0xffffffffu, s, 2);
    s += __shfl_xor_sync(0xffffffffu, s, 4);   // octet-closed: lanes 0-7 only mix
    const float w = __fdividef(e, s);

    if (lane < TOPK) {
        const size_t o = (size_t)token * TOPK + lane;
        out_w[o] = w;
        out_i[o] = (float)(cv >> 24);
    }
}

extern "C" void kernel_launch(void* const* d_in, const int* in_sizes, int n_in,
                              void* d_out, int out_size) {
    (void)n_in; (void)out_size;
    const float* gate = (const float*)d_in[0];
    const int tokens = in_sizes[0] / NUM_EXPERTS;

    float* out_w = (float*)d_out;
    float* out_i = out_w + (size_t)tokens * TOPK;

    const int threads = WARPS_PER_BLOCK * 32;
    const int blocks = (tokens + WARPS_PER_BLOCK - 1) / WARPS_PER_BLOCK;
    topk_softmax_kernel<<<blocks, threads>>>(gate, out_w, out_i, tokens);
}